// round 16
// baseline (speedup 1.0000x reference)
#include <cuda_runtime.h>
#include <cuda_bf16.h>
#include <math.h>

// Problem constants (fixed shapes per reference)
#define B_   32
#define CI_  512
#define H_   50
#define W_   37
#define HW_  1850
#define AMAX 16650
#define MAXG 32
#define KTOT 4608            // 9 taps * 512 ci

#define OFF_LOC  (B_*18*HW_)            // 1,065,600
#define OFF_LCLS (OFF_LOC + B_*36*HW_)  // 3,196,800
#define LOSS_BLOCKS 256

// ---------------------------------------------------------------------------
// Device scratch (no runtime allocation allowed)
// ---------------------------------------------------------------------------
__device__ __align__(256) float g_conv1T[B_*HW_*CI_];     // conv1, n-major [b][hw][ci], tf32-rounded
__device__ __align__(256) float g_featsT[B_*HW_*CI_];     // feats, n-major, tf32-rounded
__device__ __align__(256) float g_wT[CI_*KTOT];           // W3 [co][tap*512+ci], tf32
__device__ float g_cls[B_*18*HW_];
__device__ int   g_labels[B_*AMAX];
__device__ int   g_matched[B_*AMAX];
__device__ float g_partial[LOSS_BLOCKS*2];

// ---------------------------------------------------------------------------
// helpers
// ---------------------------------------------------------------------------
__device__ __forceinline__ unsigned smem_u32(const void* p) {
    unsigned a;
    asm("{ .reg .u64 t; cvta.to.shared.u64 t, %1; cvt.u32.u64 %0, t; }" : "=r"(a) : "l"(p));
    return a;
}
__device__ __forceinline__ float rna_tf32(float x) {
    float y;
    asm("cvt.rna.tf32.f32 %0, %1;" : "=f"(y) : "f"(x));
    return y;
}

#define CP16(dst, src, sz) \
    asm volatile("cp.async.cg.shared.global [%0], [%1], 16, %2;" \
                 :: "r"(dst), "l"(src), "r"(sz) : "memory")
#define CP_COMMIT() asm volatile("cp.async.commit_group;" ::: "memory")
#define CP_WAIT1()  asm volatile("cp.async.wait_group 1;" ::: "memory")

// m16n8k8 tf32 MMA (sm_80+ PTX, arch-neutral -> legacy HMMA on Blackwell)
#define MMA_TF32(c, a, bfr) \
    asm volatile("mma.sync.aligned.m16n8k8.row.col.f32.tf32.tf32.f32 " \
        "{%0,%1,%2,%3}, {%4,%5,%6,%7}, {%8,%9}, {%0,%1,%2,%3};" \
        : "+f"((c)[0]), "+f"((c)[1]), "+f"((c)[2]), "+f"((c)[3]) \
        : "r"((a)[0]), "r"((a)[1]), "r"((a)[2]), "r"((a)[3]), \
          "r"((bfr)[0]), "r"((bfr)[1]))

// ---------------------------------------------------------------------------
// P1: weight prep — tf32-round W3, layout [co][tap*512+ci]
// ---------------------------------------------------------------------------
__global__ void wprep_kernel(const float* __restrict__ W3) {
    int idx = blockIdx.x * blockDim.x + threadIdx.x;
    if (idx >= CI_ * KTOT) return;
    int co = idx / KTOT, r = idx % KTOT;
    int tap = r / CI_, ci = r % CI_;
    g_wT[idx] = rna_tf32(W3[(co * CI_ + ci) * 9 + tap]);
}

// ---------------------------------------------------------------------------
// P2: feats transpose to [b][hw][ci] with tf32 rounding
// ---------------------------------------------------------------------------
__global__ __launch_bounds__(256)
void transpose_kernel(const float* __restrict__ feats) {
    __shared__ float tile[32][33];
    const int b = blockIdx.z;
    const int hw0 = blockIdx.x * 32, ci0 = blockIdx.y * 32;
    const int tx = threadIdx.x % 32, ty = threadIdx.x / 32;  // 32 x 8
#pragma unroll
    for (int i = 0; i < 4; i++) {
        int ci = ci0 + ty + i * 8, hw = hw0 + tx;
        tile[ty + i * 8][tx] = (hw < HW_) ? feats[((size_t)(b * CI_ + ci)) * HW_ + hw] : 0.f;
    }
    __syncthreads();
#pragma unroll
    for (int i = 0; i < 4; i++) {
        int hw = hw0 + ty + i * 8, ci = ci0 + tx;
        if (hw < HW_)
            g_featsT[((size_t)b * HW_ + hw) * CI_ + ci] = rna_tf32(tile[tx][ty + i * 8]);
    }
}

// ---------------------------------------------------------------------------
// K1: 3x3 conv as implicit GEMM on warp-level tf32 MMA (uncompensated).
// Grid (8 ntiles, 32 b, 4 cog). CTA: 128co x 256n, 8 warps in 2(co) x 4(n),
// warp tile 64co x 64n. K=4608 in 288 chunks of 16.
// Stage (30720 B): A[128 rows][20 floats] @0, B[256 rows][20 floats] @10240.
// Epilogue stores n-major, tf32-rounded (consumed only by 1x1 MMA).
// ---------------------------------------------------------------------------
#define STAGE_B   30720
#define STAGE_F   7680
#define CONV_SMEM (2 * STAGE_B)
#define NCHUNK    288

__global__ __launch_bounds__(256)
void conv_mma_kernel(const float* __restrict__ b3) {
    extern __shared__ float smf[];
    const unsigned sb = smem_u32(smf);
    const int ntile = blockIdx.x, b = blockIdx.y, cog = blockIdx.z;
    const int n0 = ntile * 256;
    const int t = threadIdx.x;
    const int lane = t & 31, wid = t >> 5;
    const int g = lane >> 2, tig = lane & 3;
    const int wm = wid & 1, wn = wid >> 1;     // warp tile: 64co x 64n

    // A: 2 float4 per chunk per thread (128 rows x 4 quads)
    const float* asrc[2];
    unsigned adst[2];
#pragma unroll
    for (int j = 0; j < 2; j++) {
        int i = t + j * 256;
        int row = i >> 2, q = i & 3;
        asrc[j] = g_wT + (size_t)(cog * 128 + row) * KTOT + q * 4;
        adst[j] = sb + row * 80 + q * 16;
    }
    // B: 4 float4 per chunk; row = t (256 rows)
    const int bn = n0 + t;
    const int hh = bn / 37, ww = bn % 37;
    const unsigned bdst = sb + 10240 + t * 80;

    float acc[4][8][4];
#pragma unroll
    for (int mt = 0; mt < 4; mt++)
#pragma unroll
        for (int nt = 0; nt < 8; nt++)
#pragma unroll
            for (int e = 0; e < 4; e++) acc[mt][nt][e] = 0.f;

#define ISSUE(sc) do { \
        int _tap = (sc) >> 5, _ci0 = ((sc) & 31) << 4; \
        unsigned _bb = ((sc) & 1) * STAGE_B; \
        int _koff = _tap * CI_ + _ci0; \
        CP16(adst[0] + _bb, asrc[0] + _koff, 16); \
        CP16(adst[1] + _bb, asrc[1] + _koff, 16); \
        int _hp = hh + _tap / 3 - 1, _wp = ww + _tap % 3 - 1; \
        bool _v = (bn < HW_) && _hp >= 0 && _hp < H_ && _wp >= 0 && _wp < W_; \
        unsigned _sz = _v ? 16u : 0u; \
        const float* _bs = _v ? (g_featsT + ((size_t)b * HW_ + _hp * 37 + _wp) * CI_ + _ci0) \
                              : g_featsT; \
        CP16(bdst + _bb,      _bs,      _sz); \
        CP16(bdst + 16 + _bb, _bs + 4,  _sz); \
        CP16(bdst + 32 + _bb, _bs + 8,  _sz); \
        CP16(bdst + 48 + _bb, _bs + 12, _sz); \
    } while (0)

    ISSUE(0);
    CP_COMMIT();

    for (int s = 0; s < NCHUNK; s++) {
        if (s + 1 < NCHUNK) ISSUE(s + 1);
        CP_COMMIT();
        CP_WAIT1();
        __syncthreads();

        const float* St = smf + (s & 1) * STAGE_F;
        const float* Bs = St + 2560;
#pragma unroll
        for (int k8 = 0; k8 < 2; k8++) {
            const int k0 = k8 * 8;
            unsigned bfr[8][2];
#pragma unroll
            for (int nt = 0; nt < 8; nt++) {
                int nl = wn * 64 + nt * 8 + g;
                bfr[nt][0] = __float_as_uint(Bs[nl * 20 + k0 + tig]);
                bfr[nt][1] = __float_as_uint(Bs[nl * 20 + k0 + tig + 4]);
            }
            unsigned afr[4][4];
#pragma unroll
            for (int mt = 0; mt < 4; mt++) {
                int r0 = wm * 64 + mt * 16 + g;
                afr[mt][0] = __float_as_uint(St[r0 * 20 + k0 + tig]);
                afr[mt][1] = __float_as_uint(St[(r0 + 8) * 20 + k0 + tig]);
                afr[mt][2] = __float_as_uint(St[r0 * 20 + k0 + tig + 4]);
                afr[mt][3] = __float_as_uint(St[(r0 + 8) * 20 + k0 + tig + 4]);
            }
#pragma unroll
            for (int mt = 0; mt < 4; mt++)
#pragma unroll
                for (int nt = 0; nt < 8; nt++)
                    MMA_TF32(acc[mt][nt], afr[mt], bfr[nt]);
        }
        __syncthreads();
    }

    // ---- epilogue: bias + ReLU + tf32-round + n-major store ----
#pragma unroll
    for (int mt = 0; mt < 4; mt++) {
        const int co = cog * 128 + wm * 64 + mt * 16 + g;
        const float bias0 = b3[co], bias8 = b3[co + 8];
#pragma unroll
        for (int nt = 0; nt < 8; nt++) {
            const int n = n0 + wn * 64 + nt * 8 + 2 * tig;
            if (n < HW_) {
                float* p = &g_conv1T[((size_t)b * HW_ + n) * CI_];
                p[co]     = rna_tf32(fmaxf(acc[mt][nt][0] + bias0, 0.f));
                p[co + 8] = rna_tf32(fmaxf(acc[mt][nt][2] + bias8, 0.f));
            }
            if (n + 1 < HW_) {
                float* p = &g_conv1T[((size_t)b * HW_ + n + 1) * CI_];
                p[co]     = rna_tf32(fmaxf(acc[mt][nt][1] + bias0, 0.f));
                p[co + 8] = rna_tf32(fmaxf(acc[mt][nt][3] + bias8, 0.f));
            }
        }
    }
#undef ISSUE
}

// ---------------------------------------------------------------------------
// K2: fused 1x1 convs as tf32 MMA. Grid (15 ntiles, 32 b).
// CTA: 64co(54 real, zero-padded) x 128n, K=512 in 32 chunks of 16.
// Stage (15360 B): A[64][20] @0, B[128][20] @5120.
// ---------------------------------------------------------------------------
#define C1_STAGE_B 15360
#define C1_STAGE_F 3840
#define C1_SMEM    (2 * C1_STAGE_B)

__global__ __launch_bounds__(256)
void conv1x1_mma_kernel(const float* __restrict__ Wcls, const float* __restrict__ bcls,
                        const float* __restrict__ Wloc, const float* __restrict__ bloc,
                        float* __restrict__ out) {
    extern __shared__ float smf[];
    const unsigned sb = smem_u32(smf);
    const int ntile = blockIdx.x, b = blockIdx.y;
    const int n0 = ntile * 128;
    const int t = threadIdx.x;
    const int lane = t & 31, wid = t >> 5;
    const int g = lane >> 2, tig = lane & 3;
    const int wm = wid & 1, wn = wid >> 1;     // warp tile: 32co x 32n

    // A: 1 float4 per chunk per thread (64 rows x 4 quads)
    const int arow = t >> 2, aq = t & 3;
    const float* asrc;
    unsigned asz = 16;
    if (arow < 18)      asrc = Wcls + arow * CI_ + aq * 4;
    else if (arow < 54) asrc = Wloc + (arow - 18) * CI_ + aq * 4;
    else { asrc = Wcls; asz = 0; }
    const unsigned adst = sb + arow * 80 + aq * 16;

    // B: 2 float4 per chunk; row r = t>>1
    const int br = t >> 1, bq = t & 1;
    const int bn = n0 + br;
    const unsigned bsz = (bn < HW_) ? 16u : 0u;
    const float* bsrc = g_conv1T + ((size_t)b * HW_ + (bn < HW_ ? bn : 0)) * CI_ + bq * 8;
    const unsigned bdst = sb + 5120 + br * 80 + bq * 32;

    float acc[2][4][4];
#pragma unroll
    for (int mt = 0; mt < 2; mt++)
#pragma unroll
        for (int nt = 0; nt < 4; nt++)
#pragma unroll
            for (int e = 0; e < 4; e++) acc[mt][nt][e] = 0.f;

#define ISSUE1(sc) do { \
        int _k = (sc) * 16; \
        unsigned _bb = ((sc) & 1) * C1_STAGE_B; \
        CP16(adst + _bb, asrc + _k, asz); \
        CP16(bdst + _bb, bsrc + _k, bsz); \
        CP16(bdst + 16 + _bb, bsrc + _k + 4, bsz); \
    } while (0)

    ISSUE1(0);
    CP_COMMIT();

    for (int s = 0; s < 32; s++) {
        if (s + 1 < 32) ISSUE1(s + 1);
        CP_COMMIT();
        CP_WAIT1();
        __syncthreads();

        const float* St = smf + (s & 1) * C1_STAGE_F;
        const float* Bs = St + 1280;
#pragma unroll
        for (int k8 = 0; k8 < 2; k8++) {
            const int k0 = k8 * 8;
            unsigned bfr[4][2];
#pragma unroll
            for (int nt = 0; nt < 4; nt++) {
                int nl = wn * 32 + nt * 8 + g;
                bfr[nt][0] = __float_as_uint(Bs[nl * 20 + k0 + tig]);
                bfr[nt][1] = __float_as_uint(Bs[nl * 20 + k0 + tig + 4]);
            }
            unsigned afr[2][4];
#pragma unroll
            for (int mt = 0; mt < 2; mt++) {
                int r0 = wm * 32 + mt * 16 + g;
                afr[mt][0] = __float_as_uint(St[r0 * 20 + k0 + tig]);
                afr[mt][1] = __float_as_uint(St[(r0 + 8) * 20 + k0 + tig]);
                afr[mt][2] = __float_as_uint(St[r0 * 20 + k0 + tig + 4]);
                afr[mt][3] = __float_as_uint(St[(r0 + 8) * 20 + k0 + tig + 4]);
            }
#pragma unroll
            for (int mt = 0; mt < 2; mt++)
#pragma unroll
                for (int nt = 0; nt < 4; nt++)
                    MMA_TF32(acc[mt][nt], afr[mt], bfr[nt]);
        }
        __syncthreads();
    }

    // ---- epilogue: route to g_cls (co<18) or loc out (18<=co<54) ----
#pragma unroll
    for (int mt = 0; mt < 2; mt++) {
#pragma unroll
        for (int half = 0; half < 2; half++) {
            const int co = wm * 32 + mt * 16 + g + half * 8;
            if (co >= 54) continue;
            const float bias = (co < 18) ? bcls[co] : bloc[co - 18];
            float* dst = (co < 18) ? &g_cls[(b * 18 + co) * HW_]
                                   : &out[OFF_LOC + (b * 36 + (co - 18)) * HW_];
#pragma unroll
            for (int nt = 0; nt < 4; nt++) {
                const int n = n0 + wn * 32 + nt * 8 + 2 * tig;
                if (n < HW_)     dst[n]     = acc[mt][nt][half * 2]     + bias;
                if (n + 1 < HW_) dst[n + 1] = acc[mt][nt][half * 2 + 1] + bias;
            }
        }
    }
#undef ISSUE1
}

// ---------------------------------------------------------------------------
// K3: paired softmax
// ---------------------------------------------------------------------------
__global__ void softmax_kernel(float* __restrict__ out) {
    int idx = blockIdx.x * blockDim.x + threadIdx.x;
    if (idx >= B_ * 9 * HW_) return;
    int p = idx % HW_;
    int r = idx / HW_;
    int c = r % 9, b = r / 9;
    float a0 = g_cls[(b * 18 + c) * HW_ + p];
    float a1 = g_cls[(b * 18 + c + 9) * HW_ + p];
    float m = fmaxf(a0, a1);
    float e0 = expf(a0 - m), e1 = expf(a1 - m);
    float inv = 1.f / (e0 + e1);
    out[(b * 18 + c) * HW_ + p]     = e0 * inv;
    out[(b * 18 + c + 9) * HW_ + p] = e1 * inv;
}

// ---------------------------------------------------------------------------
// K4: IoU matching — EXACT round-12 kernel (proven bit-compatible labels).
// DO NOT TOUCH: even expression-level rewrites flip near-tie argmax results.
// ---------------------------------------------------------------------------
__global__ __launch_bounds__(256)
void match_kernel(const float* __restrict__ anchors, const float* __restrict__ gt,
                  int A, int G) {
    const int b = blockIdx.x;
    const int t = threadIdx.x;

    __shared__ float s_gt[MAXG * 4];
    __shared__ float s_ag[MAXG];
    if (t < G * 4) s_gt[t] = gt[b * G * 4 + t];
    __syncthreads();
    if (t < G) s_ag[t] = (s_gt[t*4+2] - s_gt[t*4]) * (s_gt[t*4+3] - s_gt[t*4+1]);
    __syncthreads();

    float bi[MAXG]; int bidx[MAXG];
    for (int g = 0; g < G; g++) { bi[g] = -1.f; bidx[g] = 0x7fffffff; }

    for (int s = t; s < A; s += 256) {
        float ax1 = anchors[s*4], ay1 = anchors[s*4+1];
        float ax2 = anchors[s*4+2], ay2 = anchors[s*4+3];
        float aa = (ax2 - ax1) * (ay2 - ay1);
        float mx = -1.f; int mg = 0;
        for (int g = 0; g < G; g++) {
            float ix1 = fmaxf(ax1, s_gt[g*4]);
            float iy1 = fmaxf(ay1, s_gt[g*4+1]);
            float ix2 = fminf(ax2, s_gt[g*4+2]);
            float iy2 = fminf(ay2, s_gt[g*4+3]);
            float iw = ix2 - ix1; if (iw < 0.f) iw = 0.f;
            float ih = iy2 - iy1; if (ih < 0.f) ih = 0.f;
            float inter = iw * ih;
            float iou = inter / fmaxf(aa + s_ag[g] - inter, 1e-8f);
            if (iou > mx) { mx = iou; mg = g; }
            if (iou > bi[g] || (iou == bi[g] && s < bidx[g])) { bi[g] = iou; bidx[g] = s; }
        }
        g_labels[b * AMAX + s]  = (mx > 0.7f) ? 1 : 0;
        g_matched[b * AMAX + s] = mg;
    }

    __shared__ float r_bi[8 * MAXG];
    __shared__ int   r_bidx[8 * MAXG];
    int lane = t & 31, wid = t >> 5;
    for (int g = 0; g < G; g++) {
        float v = bi[g]; int id = bidx[g];
        for (int off = 16; off; off >>= 1) {
            float ov = __shfl_down_sync(0xffffffff, v, off);
            int  oid = __shfl_down_sync(0xffffffff, id, off);
            if (ov > v || (ov == v && oid < id)) { v = ov; id = oid; }
        }
        if (lane == 0) { r_bi[wid * MAXG + g] = v; r_bidx[wid * MAXG + g] = id; }
    }
    __syncthreads();
    if (t < G) {
        float v = r_bi[t]; int id = r_bidx[t];
        for (int w2 = 1; w2 < 8; w2++) {
            float ov = r_bi[w2 * MAXG + t]; int oid = r_bidx[w2 * MAXG + t];
            if (ov > v || (ov == v && oid < id)) { v = ov; id = oid; }
        }
        if (id < A) g_labels[b * AMAX + id] = 1;
    }
}

// ---------------------------------------------------------------------------
// K5: losses (deterministic block partial sums)
// ---------------------------------------------------------------------------
__global__ __launch_bounds__(256)
void loss_kernel(const float* __restrict__ gt, const int* __restrict__ idxs,
                 const float* __restrict__ out, int A, int G) {
    float lc = 0.f, ll = 0.f;
    for (int idx = blockIdx.x * blockDim.x + threadIdx.x; idx < B_ * A;
         idx += gridDim.x * blockDim.x) {
        int b = idx / A, s = idx % A;
        int i = idxs[s];
        int c = i / HW_, p = i % HW_;
        float x0 = g_cls[(b * 18 + c) * HW_ + p];
        float x1 = g_cls[(b * 18 + c + 9) * HW_ + p];
        int lab = g_labels[b * AMAX + s];
        float m = fmaxf(x0, x1);
        float lse = m + logf(expf(x0 - m) + expf(x1 - m));
        lc += lse - (lab ? x1 : x0);
        if (lab) {
            int mg = g_matched[b * AMAX + s];
            int hh = i / 333, r2 = i % 333;
            int ww = r2 / 9,  k = r2 % 9;
#pragma unroll
            for (int d = 0; d < 4; d++) {
                float lv = out[OFF_LOC + (b * 36 + k * 4 + d) * HW_ + hh * W_ + ww];
                float tv = gt[(b * G + mg) * 4 + d];
                float dd = lv - tv, ad = fabsf(dd);
                ll += (ad < 1.f) ? 0.5f * dd * dd : ad - 0.5f;
            }
        }
    }
    __shared__ float sc[256], sl[256];
    sc[threadIdx.x] = lc; sl[threadIdx.x] = ll;
    __syncthreads();
    for (int o = 128; o; o >>= 1) {
        if (threadIdx.x < o) {
            sc[threadIdx.x] += sc[threadIdx.x + o];
            sl[threadIdx.x] += sl[threadIdx.x + o];
        }
        __syncthreads();
    }
    if (threadIdx.x == 0) {
        g_partial[blockIdx.x * 2]     = sc[0];
        g_partial[blockIdx.x * 2 + 1] = sl[0];
    }
}

__global__ void finalize_kernel(int A, float* __restrict__ out) {
    __shared__ float sc[256], sl[256];
    float c = 0.f, l = 0.f;
    for (int i = threadIdx.x; i < LOSS_BLOCKS; i += 256) {
        c += g_partial[i * 2];
        l += g_partial[i * 2 + 1];
    }
    sc[threadIdx.x] = c; sl[threadIdx.x] = l;
    __syncthreads();
    for (int o = 128; o; o >>= 1) {
        if (threadIdx.x < o) {
            sc[threadIdx.x] += sc[threadIdx.x + o];
            sl[threadIdx.x] += sl[threadIdx.x + o];
        }
        __syncthreads();
    }
    if (threadIdx.x == 0) {
        out[OFF_LCLS]     = sc[0] / (float)(B_ * A);
        out[OFF_LCLS + 1] = sl[0] / 256.f;
    }
}

// ---------------------------------------------------------------------------
extern "C" void kernel_launch(void* const* d_in, const int* in_sizes, int n_in,
                              void* d_out, int out_size) {
    const float* feats   = (const float*)d_in[0];
    const float* gt      = (const float*)d_in[1];
    const float* anchors = (const float*)d_in[2];
    const float* W3      = (const float*)d_in[3];
    const float* b3      = (const float*)d_in[4];
    const float* Wcls    = (const float*)d_in[5];
    const float* bcls    = (const float*)d_in[6];
    const float* Wloc    = (const float*)d_in[7];
    const float* bloc    = (const float*)d_in[8];
    const int*   idxs    = (const int*)d_in[9];
    float* out = (float*)d_out;

    const int A = in_sizes[9];
    const int G = in_sizes[1] / (B_ * 4);

    cudaFuncSetAttribute(conv_mma_kernel,
                         cudaFuncAttributeMaxDynamicSharedMemorySize, CONV_SMEM);
    cudaFuncSetAttribute(conv1x1_mma_kernel,
                         cudaFuncAttributeMaxDynamicSharedMemorySize, C1_SMEM);

    wprep_kernel<<<(CI_ * KTOT + 255) / 256, 256>>>(W3);
    transpose_kernel<<<dim3(58, 16, 32), 256>>>(feats);
    conv_mma_kernel<<<dim3(8, 32, 4), 256, CONV_SMEM>>>(b3);
    conv1x1_mma_kernel<<<dim3(15, 32), 256, C1_SMEM>>>(Wcls, bcls, Wloc, bloc, out);
    softmax_kernel<<<(B_ * 9 * HW_ + 255) / 256, 256>>>(out);
    match_kernel<<<B_, 256>>>(anchors, gt, A, G);
    loss_kernel<<<LOSS_BLOCKS, 256>>>(gt, idxs, out, A, G);
    finalize_kernel<<<1, 256>>>(A, out);
}